// round 5
// baseline (speedup 1.0000x reference)
#include <cuda_runtime.h>
#include <cuda_bf16.h>
#include <math.h>

// ---------------- problem constants ----------------
#define Nn     46080
#define Ee     737280
#define Hh     128
#define Bb     512
#define NODESC 90
#define F_IN   90
#define HLc    64
#define CAP    64

// ---------------- device scratch ----------------
__device__ float g_deg[Nn];
__device__ float g_dis[Nn];
__device__ int   g_cnt[Nn];
__device__ int   g_colp[(size_t)Nn * CAP];
__device__ float g_valp[(size_t)Nn * CAP];
__device__ float g_h1[Nn * Hh];
__device__ float g_h2[Nn * Hh];
__device__ float g_h3[Nn * Hh];
__device__ float g_lin1[Bb * HLc];

// ---------------- f32x2 packed helpers ----------------
__device__ __forceinline__ unsigned long long pk2(float a, float b) {
    unsigned long long r;
    asm("mov.b64 %0,{%1,%2};" : "=l"(r) : "f"(a), "f"(b));
    return r;
}
__device__ __forceinline__ void upk2(unsigned long long v, float& a, float& b) {
    asm("mov.b64 {%0,%1},%2;" : "=f"(a), "=f"(b) : "l"(v));
}
__device__ __forceinline__ void fma2(unsigned long long& d,
                                     unsigned long long a,
                                     unsigned long long b) {
    asm("fma.rn.f32x2 %0,%1,%2,%0;" : "+l"(d) : "l"(a), "l"(b));
}

// ---------------- prep ----------------
__global__ void init_kernel() {
    int i = blockIdx.x * blockDim.x + threadIdx.x;
    if (i < Nn) { g_deg[i] = 1.0f; g_cnt[i] = 0; }
    if (i < Bb * HLc) g_lin1[i] = 0.0f;
}
__global__ void count_kernel(const int* __restrict__ ei,
                             const float* __restrict__ ea) {
    int e = blockIdx.x * blockDim.x + threadIdx.x;
    if (e >= Ee) return;
    atomicAdd(&g_deg[ei[Ee + e]], ea[e]);
}
__global__ void dis_kernel() {
    int i = blockIdx.x * blockDim.x + threadIdx.x;
    if (i < Nn) g_dis[i] = rsqrtf(g_deg[i]);
}
__global__ void fill_kernel(const int* __restrict__ ei,
                            const float* __restrict__ ea) {
    int e = blockIdx.x * blockDim.x + threadIdx.x;
    if (e >= Ee) return;
    int s = ei[e];
    int d = ei[Ee + e];
    int slot = atomicAdd(&g_cnt[d], 1);
    if (slot < CAP) {
        size_t p = (size_t)d * CAP + slot;
        g_colp[p] = s % NODESC;
        g_valp[p] = g_dis[s] * ea[e];
    }
}

// ---------------- fused conv: relu(A_hat @ (h @ W) + b), one block = one graph ----------------
// 512 threads = 128 cols x 4 row-quarters (24 rows each, rows 90..95 zero pad).
template <int FIN>
__global__ __launch_bounds__(512, 1)
void conv_kernel(const float* __restrict__ hin,
                 const float* __restrict__ W,
                 const float* __restrict__ b,
                 float* __restrict__ hout) {
    extern __shared__ float sm[];
    float* hsT  = sm;                         // FIN * 100
    float* Wsm  = sm + FIN * 100;             // FIN * 128
    float* hw   = Wsm + FIN * 128;            // 90 * 128
    float* sdis = hw + NODESC * 128;          // 96

    const int tid = threadIdx.x;
    const int g = blockIdx.x;
    const int gbase = g * NODESC;
    const float* hg = hin + (size_t)gbase * FIN;

    if (tid < NODESC) sdis[tid] = g_dis[gbase + tid];
    for (int i = tid; i < 96 * FIN; i += 512) {
        int r = i / FIN, k = i - r * FIN;
        hsT[k * 100 + r] = (r < NODESC) ? hg[r * FIN + k] : 0.0f;
    }
    for (int i = tid; i < FIN * 128; i += 512) Wsm[i] = W[i];
    __syncthreads();

    const int col = tid & 127;
    const int rbase = (tid >> 7) * 24;
    unsigned long long acc[12];
#pragma unroll
    for (int p = 0; p < 12; p++) acc[p] = 0ull;

#pragma unroll 4
    for (int kk = 0; kk < FIN; kk++) {
        float w = Wsm[kk * 128 + col];
        unsigned long long wp = pk2(w, w);
        const ulonglong2* hp = (const ulonglong2*)&hsT[kk * 100 + rbase];
#pragma unroll
        for (int j = 0; j < 6; j++) {
            ulonglong2 hh = hp[j];
            fma2(acc[2 * j], hh.x, wp);
            fma2(acc[2 * j + 1], hh.y, wp);
        }
    }
#pragma unroll
    for (int j = 0; j < 6; j++) {
#pragma unroll
        for (int s2 = 0; s2 < 2; s2++) {
            float a, bv;
            upk2(acc[2 * j + s2], a, bv);
            int r0 = rbase + 4 * j + 2 * s2;
            if (r0 < NODESC)     hw[r0 * 128 + col] = a;
            if (r0 + 1 < NODESC) hw[(r0 + 1) * 128 + col] = bv;
        }
    }
    __syncthreads();

    // aggregate: one warp per node, lane covers float4 of the 128 cols
    const int wid = tid >> 5, lane = tid & 31;
    float4 bb = ((const float4*)b)[lane];
    for (int node = wid; node < NODESC; node += 16) {
        float dd = sdis[node];
        int cn = g_cnt[gbase + node];
        if (cn > CAP) cn = CAP;
        const int*   cp = &g_colp[(size_t)(gbase + node) * CAP];
        const float* vp = &g_valp[(size_t)(gbase + node) * CAP];
        float4 acc4 = *(const float4*)&hw[node * 128 + lane * 4];
        acc4.x *= dd; acc4.y *= dd; acc4.z *= dd; acc4.w *= dd;
        for (int e0 = 0; e0 < cn; e0 += 4) {
            int4   c4 = *(const int4*)(cp + e0);
            float4 v4 = *(const float4*)(vp + e0);
#define EDGE(J, SL, VV)                                                \
            if (e0 + J < cn) {                                         \
                const float4 h4 = *(const float4*)&hw[(SL) * 128 + lane * 4]; \
                acc4.x = fmaf(VV, h4.x, acc4.x);                       \
                acc4.y = fmaf(VV, h4.y, acc4.y);                       \
                acc4.z = fmaf(VV, h4.z, acc4.z);                       \
                acc4.w = fmaf(VV, h4.w, acc4.w);                       \
            }
            EDGE(0, c4.x, v4.x)
            EDGE(1, c4.y, v4.y)
            EDGE(2, c4.z, v4.z)
            EDGE(3, c4.w, v4.w)
#undef EDGE
        }
        float4 o;
        o.x = fmaxf(fmaf(dd, acc4.x, bb.x), 0.0f);
        o.y = fmaxf(fmaf(dd, acc4.y, bb.y), 0.0f);
        o.z = fmaxf(fmaf(dd, acc4.z, bb.z), 0.0f);
        o.w = fmaxf(fmaf(dd, acc4.w, bb.w), 0.0f);
        *(float4*)&hout[(size_t)(gbase + node) * 128 + lane * 4] = o;
    }
}

// ---------------- lin1: 32 graphs/block, split-K 18, f32x2, smem-reduced atomics ----------------
__global__ __launch_bounds__(256) void lin1_kernel(const float* __restrict__ W) {
    extern __shared__ float zs[];   // 384*36 floats = 55296 B
    const int col = threadIdx.x & 63;
    const int kl  = threadIdx.x >> 6;   // 0..3
    const int g0 = blockIdx.y * 32;
    const int kbase = blockIdx.x * 1920;
    unsigned long long acc[16];
#pragma unroll
    for (int q = 0; q < 16; q++) acc[q] = 0ull;

    for (int nb = 0; nb < 5; nb++) {
        int kb = kbase + nb * 384;
        int node = kb / 384;
        __syncthreads();
        for (int i = threadIdx.x; i < 32 * 384; i += 256) {
            int g = i / 384, r = i - g * 384;
            int layer = r >> 7, feat = r & 127;
            const float* hp = (layer == 0) ? g_h1 : (layer == 1) ? g_h2 : g_h3;
            zs[r * 36 + g] = hp[((g0 + g) * NODESC + node) * Hh + feat];
        }
        __syncthreads();
        int kbeg = kl * 96;
#pragma unroll 4
        for (int k = kbeg; k < kbeg + 96; k++) {
            float w = __ldg(&W[(kb + k) * HLc + col]);
            unsigned long long wp = pk2(w, w);
            const ulonglong2* zp = (const ulonglong2*)&zs[k * 36];
#pragma unroll
            for (int j = 0; j < 8; j++) {
                ulonglong2 zz = zp[j];
                fma2(acc[2 * j], zz.x, wp);
                fma2(acc[2 * j + 1], zz.y, wp);
            }
        }
    }
    // reduce the 4 kl partials in smem, then one atomic per (col, graph)
    __syncthreads();
    float* red = zs;   // 4*64*32 = 8192 floats, fits
#pragma unroll
    for (int j = 0; j < 8; j++) {
#pragma unroll
        for (int s2 = 0; s2 < 2; s2++) {
            float a, bv;
            upk2(acc[2 * j + s2], a, bv);
            int gg = 4 * j + 2 * s2;
            red[(kl * 64 + col) * 32 + gg]     = a;
            red[(kl * 64 + col) * 32 + gg + 1] = bv;
        }
    }
    __syncthreads();
    for (int p = threadIdx.x; p < 64 * 32; p += 256) {
        int c = p >> 5, g = p & 31;
        float s = red[(0 * 64 + c) * 32 + g] + red[(1 * 64 + c) * 32 + g] +
                  red[(2 * 64 + c) * 32 + g] + red[(3 * 64 + c) * 32 + g];
        atomicAdd(&g_lin1[(g0 + g) * HLc + c], s);
    }
}

// ---------------- head ----------------
__global__ void head_kernel(const float* __restrict__ lb,
                            const float* __restrict__ W2,
                            const float* __restrict__ b2,
                            float* __restrict__ out) {
    int g = blockIdx.x * blockDim.x + threadIdx.x;
    if (g >= Bb) return;
    float l0 = b2[0], l1 = b2[1];
    for (int j = 0; j < HLc; j++) {
        float h = fmaxf(g_lin1[g * HLc + j] + lb[j], 0.0f);
        l0 = fmaf(h, W2[j * 2 + 0], l0);
        l1 = fmaf(h, W2[j * 2 + 1], l1);
    }
    float m = fmaxf(l0, l1);
    float lse = m + logf(expf(l0 - m) + expf(l1 - m));
    out[g * 2 + 0] = l0 - lse;
    out[g * 2 + 1] = l1 - lse;
}

// ---------------- launch: inputs mapped BY SIZE ----------------
extern "C" void kernel_launch(void* const* d_in, const int* in_sizes, int n_in,
                              void* d_out, int out_size) {
    const float *x = 0, *ea = 0, *W1 = 0, *W2 = 0, *W3 = 0;
    const float *b1 = 0, *b2 = 0, *b3 = 0, *l2W = 0;
    const float *l1W = 0, *l1b = 0, *l2b = 0;
    const int *ei = 0;
    int n128 = 0, n16k = 0;

    for (int i = 0; i < n_in; i++) {
        const void* p = d_in[i];
        switch (in_sizes[i]) {
            case 4147200: x = (const float*)p; break;
            case 737280:  ea = (const float*)p; break;
            case 11520:   W1 = (const float*)p; break;
            case 16384:   if (n16k++ == 0) W2 = (const float*)p;
                          else             W3 = (const float*)p; break;
            case 128: {
                int k = n128++;
                if      (k == 0) b1 = (const float*)p;
                else if (k == 1) b2 = (const float*)p;
                else if (k == 2) b3 = (const float*)p;
                else             l2W = (const float*)p;
                break; }
            case 2211840: l1W = (const float*)p; break;
            case 64:      l1b = (const float*)p; break;
            case 2:       l2b = (const float*)p; break;
            case 1474560: ei = (const int*)p; break;
            default: break;
        }
    }
    float* out = (float*)d_out;

    float *h1, *h2, *h3;
    cudaGetSymbolAddress((void**)&h1, g_h1);
    cudaGetSymbolAddress((void**)&h2, g_h2);
    cudaGetSymbolAddress((void**)&h3, g_h3);

    const int smem90  = (F_IN * 100 + F_IN * 128 + NODESC * 128 + 96) * 4;
    const int smem128 = (Hh * 100 + Hh * 128 + NODESC * 128 + 96) * 4;
    const int smemL1  = 384 * 36 * 4;
    cudaFuncSetAttribute(conv_kernel<F_IN>,
                         cudaFuncAttributeMaxDynamicSharedMemorySize, smem90);
    cudaFuncSetAttribute(conv_kernel<Hh>,
                         cudaFuncAttributeMaxDynamicSharedMemorySize, smem128);
    cudaFuncSetAttribute(lin1_kernel,
                         cudaFuncAttributeMaxDynamicSharedMemorySize, smemL1);

    init_kernel<<<(Nn + 255) / 256, 256>>>();
    count_kernel<<<Ee / 256, 256>>>(ei, ea);
    dis_kernel<<<(Nn + 255) / 256, 256>>>();
    fill_kernel<<<Ee / 256, 256>>>(ei, ea);

    conv_kernel<F_IN><<<Bb, 512, smem90>>>(x, W1, b1, h1);
    conv_kernel<Hh><<<Bb, 512, smem128>>>(h1, W2, b2, h2);
    conv_kernel<Hh><<<Bb, 512, smem128>>>(h2, W3, b3, h3);

    lin1_kernel<<<dim3(18, 16), 256, smemL1>>>(l1W);
    head_kernel<<<2, 256>>>(l1b, l2W, l2b, out);
}

// round 6
// speedup vs baseline: 1.0079x; 1.0079x over previous
#include <cuda_runtime.h>
#include <cuda_bf16.h>
#include <math.h>

// ---------------- problem constants ----------------
#define Nn     46080
#define Ee     737280
#define Hh     128
#define Bb     512
#define NODESC 90
#define F_IN   90
#define HLc    64
#define CAP    64

// ---------------- device scratch ----------------
__device__ float g_deg[Nn];
__device__ float g_dis[Nn];
__device__ int   g_cnt[Nn];
__device__ int   g_colp[(size_t)Nn * CAP];
__device__ float g_valp[(size_t)Nn * CAP];
__device__ float g_h1[Nn * Hh];
__device__ float g_h2[Nn * Hh];
__device__ float g_h3[Nn * Hh];
__device__ float g_lin1[Bb * HLc];

// ---------------- f32x2 packed helpers ----------------
__device__ __forceinline__ unsigned long long pk2(float a, float b) {
    unsigned long long r;
    asm("mov.b64 %0,{%1,%2};" : "=l"(r) : "f"(a), "f"(b));
    return r;
}
__device__ __forceinline__ void upk2(unsigned long long v, float& a, float& b) {
    asm("mov.b64 {%0,%1},%2;" : "=f"(a), "=f"(b) : "l"(v));
}
__device__ __forceinline__ void fma2(unsigned long long& d,
                                     unsigned long long a,
                                     unsigned long long b) {
    asm("fma.rn.f32x2 %0,%1,%2,%0;" : "+l"(d) : "l"(a), "l"(b));
}

// ---------------- prep ----------------
__global__ void init_kernel() {
    int i = blockIdx.x * blockDim.x + threadIdx.x;
    if (i < Nn) { g_deg[i] = 1.0f; g_cnt[i] = 0; }
    if (i < Bb * HLc) g_lin1[i] = 0.0f;
}
__global__ void count_kernel(const int* __restrict__ ei,
                             const float* __restrict__ ea) {
    int e = blockIdx.x * blockDim.x + threadIdx.x;
    if (e >= Ee) return;
    atomicAdd(&g_deg[ei[Ee + e]], ea[e]);
}
__global__ void dis_kernel() {
    int i = blockIdx.x * blockDim.x + threadIdx.x;
    if (i < Nn) g_dis[i] = rsqrtf(g_deg[i]);
}
__global__ void fill_kernel(const int* __restrict__ ei,
                            const float* __restrict__ ea) {
    int e = blockIdx.x * blockDim.x + threadIdx.x;
    if (e >= Ee) return;
    int s = ei[e];
    int d = ei[Ee + e];
    int slot = atomicAdd(&g_cnt[d], 1);
    if (slot < CAP) {
        size_t p = (size_t)d * CAP + slot;
        g_colp[p] = s % NODESC;
        g_valp[p] = g_dis[s] * ea[e];
    }
}

// ---------------- fused conv: relu(A_hat @ (h @ W) + b), one block = one graph ----------------
// 512 threads = 128 cols x 4 row-quarters (24 rows each, rows 90..95 zero pad).
template <int FIN>
__global__ __launch_bounds__(512, 1)
void conv_kernel(const float* __restrict__ hin,
                 const float* __restrict__ W,
                 const float* __restrict__ b,
                 float* __restrict__ hout) {
    extern __shared__ float sm[];
    float* hsT  = sm;                         // FIN * 100
    float* Wsm  = sm + FIN * 100;             // FIN * 128
    float* hw   = Wsm + FIN * 128;            // 90 * 128
    float* sdis = hw + NODESC * 128;          // 96

    const int tid = threadIdx.x;
    const int g = blockIdx.x;
    const int gbase = g * NODESC;
    const float* hg = hin + (size_t)gbase * FIN;

    if (tid < NODESC) sdis[tid] = g_dis[gbase + tid];
    for (int i = tid; i < 96 * FIN; i += 512) {
        int r = i / FIN, k = i - r * FIN;
        hsT[k * 100 + r] = (r < NODESC) ? hg[r * FIN + k] : 0.0f;
    }
    for (int i = tid; i < FIN * 128; i += 512) Wsm[i] = W[i];
    __syncthreads();

    const int col = tid & 127;
    const int rbase = (tid >> 7) * 24;
    unsigned long long acc[12];
#pragma unroll
    for (int p = 0; p < 12; p++) acc[p] = 0ull;

#pragma unroll 4
    for (int kk = 0; kk < FIN; kk++) {
        float w = Wsm[kk * 128 + col];
        unsigned long long wp = pk2(w, w);
        const ulonglong2* hp = (const ulonglong2*)&hsT[kk * 100 + rbase];
#pragma unroll
        for (int j = 0; j < 6; j++) {
            ulonglong2 hh = hp[j];
            fma2(acc[2 * j], hh.x, wp);
            fma2(acc[2 * j + 1], hh.y, wp);
        }
    }
#pragma unroll
    for (int j = 0; j < 6; j++) {
#pragma unroll
        for (int s2 = 0; s2 < 2; s2++) {
            float a, bv;
            upk2(acc[2 * j + s2], a, bv);
            int r0 = rbase + 4 * j + 2 * s2;
            if (r0 < NODESC)     hw[r0 * 128 + col] = a;
            if (r0 + 1 < NODESC) hw[(r0 + 1) * 128 + col] = bv;
        }
    }
    __syncthreads();

    // aggregate: one warp per node, lane covers float4 of the 128 cols
    const int wid = tid >> 5, lane = tid & 31;
    float4 bb = ((const float4*)b)[lane];
    for (int node = wid; node < NODESC; node += 16) {
        float dd = sdis[node];
        int cn = g_cnt[gbase + node];
        if (cn > CAP) cn = CAP;
        const int*   cp = &g_colp[(size_t)(gbase + node) * CAP];
        const float* vp = &g_valp[(size_t)(gbase + node) * CAP];
        float4 acc4 = *(const float4*)&hw[node * 128 + lane * 4];
        acc4.x *= dd; acc4.y *= dd; acc4.z *= dd; acc4.w *= dd;
        for (int e0 = 0; e0 < cn; e0 += 4) {
            int4   c4 = *(const int4*)(cp + e0);
            float4 v4 = *(const float4*)(vp + e0);
#define EDGE(J, SL, VV)                                                \
            if (e0 + J < cn) {                                         \
                const float4 h4 = *(const float4*)&hw[(SL) * 128 + lane * 4]; \
                acc4.x = fmaf(VV, h4.x, acc4.x);                       \
                acc4.y = fmaf(VV, h4.y, acc4.y);                       \
                acc4.z = fmaf(VV, h4.z, acc4.z);                       \
                acc4.w = fmaf(VV, h4.w, acc4.w);                       \
            }
            EDGE(0, c4.x, v4.x)
            EDGE(1, c4.y, v4.y)
            EDGE(2, c4.z, v4.z)
            EDGE(3, c4.w, v4.w)
#undef EDGE
        }
        float4 o;
        o.x = fmaxf(fmaf(dd, acc4.x, bb.x), 0.0f);
        o.y = fmaxf(fmaf(dd, acc4.y, bb.y), 0.0f);
        o.z = fmaxf(fmaf(dd, acc4.z, bb.z), 0.0f);
        o.w = fmaxf(fmaf(dd, acc4.w, bb.w), 0.0f);
        *(float4*)&hout[(size_t)(gbase + node) * 128 + lane * 4] = o;
    }
}

// ---------------- lin1: 32 graphs/block, split-K 18, f32x2, smem-reduced atomics ----------------
__global__ __launch_bounds__(256) void lin1_kernel(const float* __restrict__ W) {
    extern __shared__ float zs[];   // 384*36 floats = 55296 B
    const int col = threadIdx.x & 63;
    const int kl  = threadIdx.x >> 6;   // 0..3
    const int g0 = blockIdx.y * 32;
    const int kbase = blockIdx.x * 1920;
    unsigned long long acc[16];
#pragma unroll
    for (int q = 0; q < 16; q++) acc[q] = 0ull;

    for (int nb = 0; nb < 5; nb++) {
        int kb = kbase + nb * 384;
        int node = kb / 384;
        __syncthreads();
        for (int i = threadIdx.x; i < 32 * 384; i += 256) {
            int g = i / 384, r = i - g * 384;
            int layer = r >> 7, feat = r & 127;
            const float* hp = (layer == 0) ? g_h1 : (layer == 1) ? g_h2 : g_h3;
            zs[r * 36 + g] = hp[((g0 + g) * NODESC + node) * Hh + feat];
        }
        __syncthreads();
        int kbeg = kl * 96;
#pragma unroll 4
        for (int k = kbeg; k < kbeg + 96; k++) {
            float w = __ldg(&W[(kb + k) * HLc + col]);
            unsigned long long wp = pk2(w, w);
            const ulonglong2* zp = (const ulonglong2*)&zs[k * 36];
#pragma unroll
            for (int j = 0; j < 8; j++) {
                ulonglong2 zz = zp[j];
                fma2(acc[2 * j], zz.x, wp);
                fma2(acc[2 * j + 1], zz.y, wp);
            }
        }
    }
    // reduce the 4 kl partials in smem, then one atomic per (col, graph)
    __syncthreads();
    float* red = zs;   // 4*64*32 = 8192 floats, fits
#pragma unroll
    for (int j = 0; j < 8; j++) {
#pragma unroll
        for (int s2 = 0; s2 < 2; s2++) {
            float a, bv;
            upk2(acc[2 * j + s2], a, bv);
            int gg = 4 * j + 2 * s2;
            red[(kl * 64 + col) * 32 + gg]     = a;
            red[(kl * 64 + col) * 32 + gg + 1] = bv;
        }
    }
    __syncthreads();
    for (int p = threadIdx.x; p < 64 * 32; p += 256) {
        int c = p >> 5, g = p & 31;
        float s = red[(0 * 64 + c) * 32 + g] + red[(1 * 64 + c) * 32 + g] +
                  red[(2 * 64 + c) * 32 + g] + red[(3 * 64 + c) * 32 + g];
        atomicAdd(&g_lin1[(g0 + g) * HLc + c], s);
    }
}

// ---------------- head ----------------
__global__ void head_kernel(const float* __restrict__ lb,
                            const float* __restrict__ W2,
                            const float* __restrict__ b2,
                            float* __restrict__ out) {
    int g = blockIdx.x * blockDim.x + threadIdx.x;
    if (g >= Bb) return;
    float l0 = b2[0], l1 = b2[1];
    for (int j = 0; j < HLc; j++) {
        float h = fmaxf(g_lin1[g * HLc + j] + lb[j], 0.0f);
        l0 = fmaf(h, W2[j * 2 + 0], l0);
        l1 = fmaf(h, W2[j * 2 + 1], l1);
    }
    float m = fmaxf(l0, l1);
    float lse = m + logf(expf(l0 - m) + expf(l1 - m));
    out[g * 2 + 0] = l0 - lse;
    out[g * 2 + 1] = l1 - lse;
}

// ---------------- launch: inputs mapped BY SIZE ----------------
extern "C" void kernel_launch(void* const* d_in, const int* in_sizes, int n_in,
                              void* d_out, int out_size) {
    const float *x = 0, *ea = 0, *W1 = 0, *W2 = 0, *W3 = 0;
    const float *b1 = 0, *b2 = 0, *b3 = 0, *l2W = 0;
    const float *l1W = 0, *l1b = 0, *l2b = 0;
    const int *ei = 0;
    int n128 = 0, n16k = 0;

    for (int i = 0; i < n_in; i++) {
        const void* p = d_in[i];
        switch (in_sizes[i]) {
            case 4147200: x = (const float*)p; break;
            case 737280:  ea = (const float*)p; break;
            case 11520:   W1 = (const float*)p; break;
            case 16384:   if (n16k++ == 0) W2 = (const float*)p;
                          else             W3 = (const float*)p; break;
            case 128: {
                int k = n128++;
                if      (k == 0) b1 = (const float*)p;
                else if (k == 1) b2 = (const float*)p;
                else if (k == 2) b3 = (const float*)p;
                else             l2W = (const float*)p;
                break; }
            case 2211840: l1W = (const float*)p; break;
            case 64:      l1b = (const float*)p; break;
            case 2:       l2b = (const float*)p; break;
            case 1474560: ei = (const int*)p; break;
            default: break;
        }
    }
    float* out = (float*)d_out;

    float *h1, *h2, *h3;
    cudaGetSymbolAddress((void**)&h1, g_h1);
    cudaGetSymbolAddress((void**)&h2, g_h2);
    cudaGetSymbolAddress((void**)&h3, g_h3);

    const int smem90  = (F_IN * 100 + F_IN * 128 + NODESC * 128 + 96) * 4;
    const int smem128 = (Hh * 100 + Hh * 128 + NODESC * 128 + 96) * 4;
    const int smemL1  = 384 * 36 * 4;
    cudaFuncSetAttribute(conv_kernel<F_IN>,
                         cudaFuncAttributeMaxDynamicSharedMemorySize, smem90);
    cudaFuncSetAttribute(conv_kernel<Hh>,
                         cudaFuncAttributeMaxDynamicSharedMemorySize, smem128);
    cudaFuncSetAttribute(lin1_kernel,
                         cudaFuncAttributeMaxDynamicSharedMemorySize, smemL1);

    init_kernel<<<(Nn + 255) / 256, 256>>>();
    count_kernel<<<Ee / 256, 256>>>(ei, ea);
    dis_kernel<<<(Nn + 255) / 256, 256>>>();
    fill_kernel<<<Ee / 256, 256>>>(ei, ea);

    conv_kernel<F_IN><<<Bb, 512, smem90>>>(x, W1, b1, h1);
    conv_kernel<Hh><<<Bb, 512, smem128>>>(h1, W2, b2, h2);
    conv_kernel<Hh><<<Bb, 512, smem128>>>(h2, W3, b3, h3);

    lin1_kernel<<<dim3(18, 16), 256, smemL1>>>(l1W);
    head_kernel<<<2, 256>>>(l1b, l2W, l2b, out);
}